// round 1
// baseline (speedup 1.0000x reference)
#include <cuda_runtime.h>

// Problem constants
#define N_ 2
#define C_ 64
#define M_ 4800
#define K_ 64
#define EPS_ 1e-5f

// ---------------- device scratch (no allocation allowed) ----------------
__device__ __align__(16) float g_B0p[N_ * C_ * M_];   // s0[c] * (W0q @ query)   [n][c][m]
__device__ __align__(16) float g_A0p[N_ * C_ * K_];   // s0*(W0s @ scene) + t0   [n][c][k]
__device__ __align__(16) float g_T1a[N_ * C_ * K_];   // s1a*(W1a_xyz @ sx)+t1a  [n][c][k]
__device__ __align__(16) float g_Ts [N_ * C_ * K_];   // Wskip_xyz @ sx          [n][c][k]
__device__ __align__(16) float g_WaT[C_ * C_];        // (s1a[c]*W1a[c][j]) transposed [j][c]
__device__ __align__(16) float g_WbT[C_ * C_];        // (s1b[c]*W1b[c][j]) transposed [j][c]
__device__ __align__(16) float g_WsT[C_ * C_];        // Wskip[c][j] transposed        [j][c]
__device__ float g_s0[C_], g_t0[C_], g_s1a[C_], g_t1a[C_], g_t1b[C_];

// ---------------- prep 1: BN folds + transposed/scaled weights ----------------
__global__ void prep_weights(
    const float* __restrict__ W1a, const float* __restrict__ W1b,
    const float* __restrict__ Wskip,
    const float* __restrict__ g0, const float* __restrict__ b0,
    const float* __restrict__ m0, const float* __restrict__ v0,
    const float* __restrict__ g1a, const float* __restrict__ b1a,
    const float* __restrict__ m1a, const float* __restrict__ v1a,
    const float* __restrict__ g1b, const float* __restrict__ b1b,
    const float* __restrict__ m1b, const float* __restrict__ v1b)
{
    __shared__ float s1a_s[C_], s1b_s[C_];
    int t = threadIdx.x;
    if (t < C_) {
        float s = g0[t] * rsqrtf(v0[t] + EPS_);
        g_s0[t] = s; g_t0[t] = b0[t] - m0[t] * s;
        float sa = g1a[t] * rsqrtf(v1a[t] + EPS_);
        s1a_s[t] = sa; g_s1a[t] = sa; g_t1a[t] = b1a[t] - m1a[t] * sa;
        float sb = g1b[t] * rsqrtf(v1b[t] + EPS_);
        s1b_s[t] = sb; g_t1b[t] = b1b[t] - m1b[t] * sb;
    }
    __syncthreads();
    for (int i = t; i < C_ * C_; i += blockDim.x) {
        int j = i >> 6, c = i & 63;          // g_W?T[j*64 + c]
        g_WaT[i] = s1a_s[c] * W1a[c * 67 + j];
        g_WbT[i] = s1b_s[c] * W1b[c * 64 + j];
        g_WsT[i] = Wskip[c * 67 + j];
    }
}

// ---------------- prep 2: per-(n,k) tensors (A0', T1a', Ts) ----------------
__global__ void prep_nk(
    const float* __restrict__ scene_rgb,   // (N,C,1,K)
    const float* __restrict__ scene_xyz,   // (N,3,1,K)
    const float* __restrict__ mask,        // (N,1,1,K)
    const float* __restrict__ W0,          // (C,2C)
    const float* __restrict__ W1a,         // (C,C+3)
    const float* __restrict__ Wskip)       // (C,C+3)
{
    int gid = blockIdx.x * blockDim.x + threadIdx.x;   // 0 .. N*C*K-1 = 8191
    int n = gid >> 12;
    int r = gid & 4095;
    int c = r >> 6;
    int k = r & 63;
    const float* sc = scene_rgb + n * C_ * K_;
    float acc = 0.f;
#pragma unroll 8
    for (int j = 0; j < C_; ++j)
        acc = fmaf(W0[c * 2 * C_ + j], sc[j * K_ + k], acc);
    g_A0p[gid] = g_s0[c] * acc + g_t0[c];

    float mk = mask[n * K_ + k];
    float x0 = scene_xyz[n * 3 * K_ + 0 * K_ + k] * mk;
    float x1 = scene_xyz[n * 3 * K_ + 1 * K_ + k] * mk;
    float x2 = scene_xyz[n * 3 * K_ + 2 * K_ + k] * mk;
    g_T1a[gid] = g_s1a[c] * (W1a[c * 67 + 64] * x0 + W1a[c * 67 + 65] * x1 +
                             W1a[c * 67 + 66] * x2) + g_t1a[c];
    g_Ts[gid] = Wskip[c * 67 + 64] * x0 + Wskip[c * 67 + 65] * x1 +
                Wskip[c * 67 + 66] * x2;
}

// ---------------- prep 3: B0'[n][c][m] = s0[c] * (W0[:,C:] @ query) ----------------
__global__ void prep_B0(const float* __restrict__ query,   // (N,C,M,1)
                        const float* __restrict__ W0)
{
    int gid = blockIdx.x * blockDim.x + threadIdx.x;   // 0 .. N*C*M-1 = 614399
    int m = gid % M_;
    int c = (gid / M_) % C_;
    int n = gid / (M_ * C_);
    const float* q = query + n * C_ * M_ + m;
    const float* w = W0 + c * 2 * C_ + C_;
    float acc = 0.f;
#pragma unroll 8
    for (int j = 0; j < C_; ++j)
        acc = fmaf(w[j], q[j * M_], acc);
    g_B0p[gid] = g_s0[c] * acc;
}

// ---------------- fused main kernel ----------------
// One CTA handles Tm=2 m-columns: builds H (2x64x64), then three 64x64x64
// GEMMs (skip, fcn1a, fcn1b) out of shared memory, K-max, output dot.
__device__ __forceinline__ void gemm2(const float* __restrict__ sW,
                                      const float* __restrict__ sH,
                                      float* __restrict__ acc0,
                                      float* __restrict__ acc1,
                                      int tc, int tk)
{
    const float* wp = sW + tc * 4;
    const float* hp0 = sH + tk * 4;
    const float* hp1 = sH + 4096 + tk * 4;
#pragma unroll 4
    for (int j = 0; j < 64; ++j) {
        float4 w  = *reinterpret_cast<const float4*>(wp + j * 64);
        float4 h0 = *reinterpret_cast<const float4*>(hp0 + j * 64);
        float4 h1 = *reinterpret_cast<const float4*>(hp1 + j * 64);
        float wv[4] = {w.x, w.y, w.z, w.w};
        float a0[4] = {h0.x, h0.y, h0.z, h0.w};
        float a1[4] = {h1.x, h1.y, h1.z, h1.w};
#pragma unroll
        for (int ci = 0; ci < 4; ++ci) {
#pragma unroll
            for (int ki = 0; ki < 4; ++ki) {
                acc0[ci * 4 + ki] = fmaf(wv[ci], a0[ki], acc0[ci * 4 + ki]);
                acc1[ci * 4 + ki] = fmaf(wv[ci], a1[ki], acc1[ci * 4 + ki]);
            }
        }
    }
}

__global__ void __launch_bounds__(256, 2) fused_main(
    const float* __restrict__ pre_xyz,   // (N,3,M)
    const float* __restrict__ Wout,      // (3,C+3)
    float* __restrict__ out)             // (N,3,M)
{
    __shared__ __align__(16) float sW[C_ * C_];        // 16KB, reused 3x
    __shared__ __align__(16) float sH[2 * C_ * K_];    // 32KB (H, later H1)

    const int tid = threadIdx.x;
    const int bid = blockIdx.x;                 // 0..4799
    const int n = bid / (M_ / 2);
    const int m0 = (bid % (M_ / 2)) * 2;
    const int tk = tid & 15, tc = tid >> 4;

    const float* A0n = g_A0p + n * C_ * K_;
    const float* B0n = g_B0p + n * C_ * M_;

    // Phase A: load Wskip^T + build H[mi][j][k] = relu(A0'[j][k] + B0'[j][m])
    for (int i = tid; i < C_ * C_; i += 256) sW[i] = g_WsT[i];
#pragma unroll
    for (int mi = 0; mi < 2; ++mi) {
        const float* Bm = B0n + (m0 + mi);
        for (int i4 = tid; i4 < 1024; i4 += 256) {
            int j = i4 >> 4;
            float4 a = reinterpret_cast<const float4*>(A0n)[i4];
            float b = Bm[j * M_];
            float4 h;
            h.x = fmaxf(a.x + b, 0.f);
            h.y = fmaxf(a.y + b, 0.f);
            h.z = fmaxf(a.z + b, 0.f);
            h.w = fmaxf(a.w + b, 0.f);
            reinterpret_cast<float4*>(sH)[mi * 1024 + i4] = h;
        }
    }
    __syncthreads();

    // Phase B: skip GEMM, accS initialized with Ts bias (same for both mi)
    float accS0[16], accS1[16];
    {
        const float* tsb = g_Ts + n * 4096 + tk * 4;
#pragma unroll
        for (int ci = 0; ci < 4; ++ci) {
            float4 b = *reinterpret_cast<const float4*>(tsb + (tc * 4 + ci) * 64);
            accS0[ci * 4 + 0] = b.x; accS0[ci * 4 + 1] = b.y;
            accS0[ci * 4 + 2] = b.z; accS0[ci * 4 + 3] = b.w;
            accS1[ci * 4 + 0] = b.x; accS1[ci * 4 + 1] = b.y;
            accS1[ci * 4 + 2] = b.z; accS1[ci * 4 + 3] = b.w;
        }
    }
    gemm2(sW, sH, accS0, accS1, tc, tk);
    __syncthreads();

    // Phase C: load Wa^T
    for (int i = tid; i < C_ * C_; i += 256) sW[i] = g_WaT[i];
    __syncthreads();

    // Phase D: fcn1a GEMM, acc1 initialized with T1a bias
    float acc1a0[16], acc1a1[16];
    {
        const float* tab = g_T1a + n * 4096 + tk * 4;
#pragma unroll
        for (int ci = 0; ci < 4; ++ci) {
            float4 b = *reinterpret_cast<const float4*>(tab + (tc * 4 + ci) * 64);
            acc1a0[ci * 4 + 0] = b.x; acc1a0[ci * 4 + 1] = b.y;
            acc1a0[ci * 4 + 2] = b.z; acc1a0[ci * 4 + 3] = b.w;
            acc1a1[ci * 4 + 0] = b.x; acc1a1[ci * 4 + 1] = b.y;
            acc1a1[ci * 4 + 2] = b.z; acc1a1[ci * 4 + 3] = b.w;
        }
    }
    gemm2(sW, sH, acc1a0, acc1a1, tc, tk);
    __syncthreads();

    // Phase E: H1 = relu(acc1a) overwrites sH; load Wb^T
#pragma unroll
    for (int ci = 0; ci < 4; ++ci) {
        float4 h0, h1;
        h0.x = fmaxf(acc1a0[ci * 4 + 0], 0.f);
        h0.y = fmaxf(acc1a0[ci * 4 + 1], 0.f);
        h0.z = fmaxf(acc1a0[ci * 4 + 2], 0.f);
        h0.w = fmaxf(acc1a0[ci * 4 + 3], 0.f);
        h1.x = fmaxf(acc1a1[ci * 4 + 0], 0.f);
        h1.y = fmaxf(acc1a1[ci * 4 + 1], 0.f);
        h1.z = fmaxf(acc1a1[ci * 4 + 2], 0.f);
        h1.w = fmaxf(acc1a1[ci * 4 + 3], 0.f);
        *reinterpret_cast<float4*>(sH + (tc * 4 + ci) * 64 + tk * 4) = h0;
        *reinterpret_cast<float4*>(sH + 4096 + (tc * 4 + ci) * 64 + tk * 4) = h1;
    }
    for (int i = tid; i < C_ * C_; i += 256) sW[i] = g_WbT[i];
    __syncthreads();

    // Phase F: fcn1b GEMM, accB initialized with t1b[c]
    float accB0[16], accB1[16];
#pragma unroll
    for (int ci = 0; ci < 4; ++ci) {
        float tb = g_t1b[tc * 4 + ci];
#pragma unroll
        for (int ki = 0; ki < 4; ++ki) {
            accB0[ci * 4 + ki] = tb;
            accB1[ci * 4 + ki] = tb;
        }
    }
    gemm2(sW, sH, accB0, accB1, tc, tk);

    // F = relu(accB) + accS; thread-local max over 4 k's, then shfl over tk
    float fmx0[4], fmx1[4];
#pragma unroll
    for (int ci = 0; ci < 4; ++ci) {
        float v0 = fmaxf(accB0[ci * 4 + 0], 0.f) + accS0[ci * 4 + 0];
        float v1 = fmaxf(accB0[ci * 4 + 1], 0.f) + accS0[ci * 4 + 1];
        float v2 = fmaxf(accB0[ci * 4 + 2], 0.f) + accS0[ci * 4 + 2];
        float v3 = fmaxf(accB0[ci * 4 + 3], 0.f) + accS0[ci * 4 + 3];
        fmx0[ci] = fmaxf(fmaxf(v0, v1), fmaxf(v2, v3));
        float w0 = fmaxf(accB1[ci * 4 + 0], 0.f) + accS1[ci * 4 + 0];
        float w1 = fmaxf(accB1[ci * 4 + 1], 0.f) + accS1[ci * 4 + 1];
        float w2 = fmaxf(accB1[ci * 4 + 2], 0.f) + accS1[ci * 4 + 2];
        float w3 = fmaxf(accB1[ci * 4 + 3], 0.f) + accS1[ci * 4 + 3];
        fmx1[ci] = fmaxf(fmaxf(w0, w1), fmaxf(w2, w3));
    }
#pragma unroll
    for (int off = 8; off >= 1; off >>= 1) {
#pragma unroll
        for (int ci = 0; ci < 4; ++ci) {
            fmx0[ci] = fmaxf(fmx0[ci], __shfl_xor_sync(0xffffffffu, fmx0[ci], off, 16));
            fmx1[ci] = fmaxf(fmx1[ci], __shfl_xor_sync(0xffffffffu, fmx1[ci], off, 16));
        }
    }
    __syncthreads();                       // everyone done reading sW
    float* sF = sW;                        // reuse as [mi][64] max buffer
    if (tk == 0) {
#pragma unroll
        for (int ci = 0; ci < 4; ++ci) {
            sF[0 * 64 + tc * 4 + ci] = fmx0[ci];
            sF[1 * 64 + tc * 4 + ci] = fmx1[ci];
        }
    }
    __syncthreads();

    // Phase G: out[n][o][m] = Wout[o,:64] @ fmax + Wout[o,64:67] @ pre_xyz[:,m]
    int w = tid >> 5, l = tid & 31;
    if (w < 6) {
        int mi = w / 3, o = w % 3;
        int m = m0 + mi;
        float p = Wout[o * 67 + l] * sF[mi * 64 + l] +
                  Wout[o * 67 + 32 + l] * sF[mi * 64 + 32 + l];
#pragma unroll
        for (int off = 16; off >= 1; off >>= 1)
            p += __shfl_xor_sync(0xffffffffu, p, off);
        if (l == 0) {
            p += Wout[o * 67 + 64] * pre_xyz[n * 3 * M_ + 0 * M_ + m] +
                 Wout[o * 67 + 65] * pre_xyz[n * 3 * M_ + 1 * M_ + m] +
                 Wout[o * 67 + 66] * pre_xyz[n * 3 * M_ + 2 * M_ + m];
            out[n * 3 * M_ + o * M_ + m] = p;
        }
    }
}

// ---------------- launcher ----------------
extern "C" void kernel_launch(void* const* d_in, const int* in_sizes, int n_in,
                              void* d_out, int out_size)
{
    const float* query     = (const float*)d_in[0];
    const float* scene_rgb = (const float*)d_in[1];
    const float* scene_xyz = (const float*)d_in[2];
    const float* pre_xyz   = (const float*)d_in[3];
    const float* mask      = (const float*)d_in[4];
    const float* W0        = (const float*)d_in[5];
    const float* g0        = (const float*)d_in[6];
    const float* b0        = (const float*)d_in[7];
    const float* m0        = (const float*)d_in[8];
    const float* v0        = (const float*)d_in[9];
    const float* W1a       = (const float*)d_in[10];
    const float* g1a       = (const float*)d_in[11];
    const float* b1a       = (const float*)d_in[12];
    const float* m1a       = (const float*)d_in[13];
    const float* v1a       = (const float*)d_in[14];
    const float* W1b       = (const float*)d_in[15];
    const float* g1b       = (const float*)d_in[16];
    const float* b1b       = (const float*)d_in[17];
    const float* m1b       = (const float*)d_in[18];
    const float* v1b       = (const float*)d_in[19];
    const float* Wskip     = (const float*)d_in[20];
    const float* Wout      = (const float*)d_in[21];
    float* out = (float*)d_out;

    prep_weights<<<1, 256>>>(W1a, W1b, Wskip,
                             g0, b0, m0, v0,
                             g1a, b1a, m1a, v1a,
                             g1b, b1b, m1b, v1b);
    prep_nk<<<(N_ * C_ * K_) / 256, 256>>>(scene_rgb, scene_xyz, mask,
                                           W0, W1a, Wskip);
    prep_B0<<<(N_ * C_ * M_) / 256, 256>>>(query, W0);
    fused_main<<<N_ * (M_ / 2), 256>>>(pre_xyz, Wout, out);
}

// round 2
// speedup vs baseline: 1.1884x; 1.1884x over previous
#include <cuda_runtime.h>

// Problem constants
#define N_ 2
#define C_ 64
#define M_ 4800
#define K_ 64
#define EPS_ 1e-5f

// ---------------- device scratch (no allocation allowed) ----------------
__device__ __align__(16) float g_B0p[N_ * C_ * M_];   // s0[c] * (W0q @ query)   [n][c][m]
__device__ __align__(16) float g_A0p[N_ * C_ * K_];   // s0*(W0s @ scene) + t0   [n][c][k]
__device__ __align__(16) float g_T1a[N_ * C_ * K_];   // s1a*(W1a_xyz @ sx)+t1a  [n][c][k]
__device__ __align__(16) float g_Ts [N_ * C_ * K_];   // Wskip_xyz @ sx          [n][c][k]
__device__ __align__(16) float g_WaT[C_ * C_];        // (s1a[c]*W1a[c][j]) transposed [j][c]
__device__ __align__(16) float g_WbT[C_ * C_];        // (s1b[c]*W1b[c][j]) transposed [j][c]
__device__ __align__(16) float g_WsT[C_ * C_];        // Wskip[c][j] transposed        [j][c]
__device__ float g_s0[C_], g_t0[C_], g_s1a[C_], g_t1a[C_], g_t1b[C_];

// ---------------- f32x2 helpers ----------------
__device__ __forceinline__ void ffma2(unsigned long long& d,
                                      unsigned long long a,
                                      unsigned long long b) {
    asm("fma.rn.f32x2 %0, %1, %2, %0;" : "+l"(d) : "l"(a), "l"(b));
}
__device__ __forceinline__ unsigned long long dup2(float w) {
    unsigned long long r;
    asm("mov.b64 %0, {%1, %1};" : "=l"(r) : "f"(w));
    return r;
}
__device__ __forceinline__ float2 unpack2(unsigned long long v) {
    float2 r;
    asm("mov.b64 {%0, %1}, %2;" : "=f"(r.x), "=f"(r.y) : "l"(v));
    return r;
}

// ---------------- prep 1: BN folds + transposed/scaled weights ----------------
__global__ void prep_weights(
    const float* __restrict__ W1a, const float* __restrict__ W1b,
    const float* __restrict__ Wskip,
    const float* __restrict__ g0, const float* __restrict__ b0,
    const float* __restrict__ m0, const float* __restrict__ v0,
    const float* __restrict__ g1a, const float* __restrict__ b1a,
    const float* __restrict__ m1a, const float* __restrict__ v1a,
    const float* __restrict__ g1b, const float* __restrict__ b1b,
    const float* __restrict__ m1b, const float* __restrict__ v1b)
{
    __shared__ float s1a_s[C_], s1b_s[C_];
    int t = threadIdx.x;
    if (t < C_) {
        float s = g0[t] * rsqrtf(v0[t] + EPS_);
        g_s0[t] = s; g_t0[t] = b0[t] - m0[t] * s;
        float sa = g1a[t] * rsqrtf(v1a[t] + EPS_);
        s1a_s[t] = sa; g_s1a[t] = sa; g_t1a[t] = b1a[t] - m1a[t] * sa;
        float sb = g1b[t] * rsqrtf(v1b[t] + EPS_);
        s1b_s[t] = sb; g_t1b[t] = b1b[t] - m1b[t] * sb;
    }
    __syncthreads();
    for (int i = t; i < C_ * C_; i += blockDim.x) {
        int j = i >> 6, c = i & 63;          // g_W?T[j*64 + c]
        g_WaT[i] = s1a_s[c] * W1a[c * 67 + j];
        g_WbT[i] = s1b_s[c] * W1b[c * 64 + j];
        g_WsT[i] = Wskip[c * 67 + j];
    }
}

// ---------------- prep 2: per-(n,k) tensors (A0', T1a', Ts) ----------------
__global__ void prep_nk(
    const float* __restrict__ scene_rgb,   // (N,C,1,K)
    const float* __restrict__ scene_xyz,   // (N,3,1,K)
    const float* __restrict__ mask,        // (N,1,1,K)
    const float* __restrict__ W0,          // (C,2C)
    const float* __restrict__ W1a,         // (C,C+3)
    const float* __restrict__ Wskip)       // (C,C+3)
{
    int gid = blockIdx.x * blockDim.x + threadIdx.x;   // 0 .. N*C*K-1 = 8191
    int n = gid >> 12;
    int r = gid & 4095;
    int c = r >> 6;
    int k = r & 63;
    const float* sc = scene_rgb + n * C_ * K_;
    float acc = 0.f;
#pragma unroll 8
    for (int j = 0; j < C_; ++j)
        acc = fmaf(W0[c * 2 * C_ + j], sc[j * K_ + k], acc);
    g_A0p[gid] = g_s0[c] * acc + g_t0[c];

    float mk = mask[n * K_ + k];
    float x0 = scene_xyz[n * 3 * K_ + 0 * K_ + k] * mk;
    float x1 = scene_xyz[n * 3 * K_ + 1 * K_ + k] * mk;
    float x2 = scene_xyz[n * 3 * K_ + 2 * K_ + k] * mk;
    g_T1a[gid] = g_s1a[c] * (W1a[c * 67 + 64] * x0 + W1a[c * 67 + 65] * x1 +
                             W1a[c * 67 + 66] * x2) + g_t1a[c];
    g_Ts[gid] = Wskip[c * 67 + 64] * x0 + Wskip[c * 67 + 65] * x1 +
                Wskip[c * 67 + 66] * x2;
}

// ---------------- prep 3: B0'[n][c][m] = s0[c] * (W0[:,C:] @ query) ----------------
__global__ void prep_B0(const float* __restrict__ query,   // (N,C,M,1)
                        const float* __restrict__ W0)
{
    int gid = blockIdx.x * blockDim.x + threadIdx.x;   // 0 .. N*C*M-1
    int m = gid % M_;
    int c = (gid / M_) % C_;
    int n = gid / (M_ * C_);
    const float* q = query + n * C_ * M_ + m;
    const float* w = W0 + c * 2 * C_ + C_;
    float acc = 0.f;
#pragma unroll 8
    for (int j = 0; j < C_; ++j)
        acc = fmaf(w[j], q[j * M_], acc);
    g_B0p[gid] = g_s0[c] * acc;
}

// ---------------- fused main kernel ----------------
// 128 threads, CTA = 2 m-columns. Per-lane tile: 8c x 4k x 2m with k-paired
// f32x2 accumulators. Phase 1 fuses the skip + fcn1a GEMMs (shared H reads);
// phase 2 is the fcn1b GEMM against H1 = relu(fcn1a).
// Dynamic smem 64KB: sW[64][128] (Wskip|Wa rows, mat0 slot reused for Wb)
// followed by sH[2][64][64] (H, later H1).
extern "C" __global__ void __launch_bounds__(128, 2) fused_main(
    const float* __restrict__ pre_xyz,   // (N,3,M)
    const float* __restrict__ Wout,      // (3,C+3)
    float* __restrict__ out)             // (N,3,M)
{
    extern __shared__ float smem[];
    float* sW = smem;            // 8192 floats: [j*128 + mat*64 + c]
    float* sH = smem + 8192;     // 8192 floats: [mi*4096 + j*64 + k]

    const int tid  = threadIdx.x;
    const int lane = tid & 31;
    const int w    = tid >> 5;              // warp 0..3
    const int cg   = w * 2 + (lane >> 4);   // 0..7
    const int cb   = cg * 8;                // c base (8 c's per lane)
    const int tk   = lane & 15;
    const int kb   = tk * 4;                // k base (4 k's per lane)

    const int bid = blockIdx.x;
    const int n   = bid / (M_ / 2);
    const int m0  = (bid % (M_ / 2)) * 2;

    const float* A0n = g_A0p + n * 4096;
    const float* B0n = g_B0p + n * C_ * M_;

    // ---- Phase A: stage Wskip (mat slot 0) + Wa (mat slot 1); build H ----
    for (int i = tid; i < 4096; i += 128) {
        int j = i >> 6, c = i & 63;
        sW[j * 128 + c]      = g_WsT[i];
        sW[j * 128 + 64 + c] = g_WaT[i];
    }
#pragma unroll
    for (int mi = 0; mi < 2; ++mi) {
        const float* Bm = B0n + (m0 + mi);
        for (int i4 = tid; i4 < 1024; i4 += 128) {
            int j = i4 >> 4;
            float4 a = reinterpret_cast<const float4*>(A0n)[i4];
            float b = Bm[j * M_];
            float4 h;
            h.x = fmaxf(a.x + b, 0.f);
            h.y = fmaxf(a.y + b, 0.f);
            h.z = fmaxf(a.z + b, 0.f);
            h.w = fmaxf(a.w + b, 0.f);
            reinterpret_cast<float4*>(sH)[mi * 1024 + i4] = h;
        }
    }
    __syncthreads();

    // ---- bias init (packed k-pairs straight from global, L2-resident) ----
    // acc index: ci*4 + mi*2 + kp   (kp = k-pair within the lane's 4 k's)
    unsigned long long accS[32], accA[32];
    {
        const char* tsB = reinterpret_cast<const char*>(g_Ts  + n * 4096);
        const char* taB = reinterpret_cast<const char*>(g_T1a + n * 4096);
#pragma unroll
        for (int ci = 0; ci < 8; ++ci) {
            int off = ((cb + ci) * 64 + kb) * 4;
            ulonglong2 ts = *reinterpret_cast<const ulonglong2*>(tsB + off);
            ulonglong2 ta = *reinterpret_cast<const ulonglong2*>(taB + off);
            accS[ci * 4 + 0] = ts.x; accS[ci * 4 + 1] = ts.y;
            accS[ci * 4 + 2] = ts.x; accS[ci * 4 + 3] = ts.y;
            accA[ci * 4 + 0] = ta.x; accA[ci * 4 + 1] = ta.y;
            accA[ci * 4 + 2] = ta.x; accA[ci * 4 + 3] = ta.y;
        }
    }

    // ---- Phase B: fused skip + fcn1a GEMMs over j ----
#pragma unroll 2
    for (int j = 0; j < 64; ++j) {
        ulonglong2 h0 = *reinterpret_cast<const ulonglong2*>(sH + j * 64 + kb);
        ulonglong2 h1 = *reinterpret_cast<const ulonglong2*>(sH + 4096 + j * 64 + kb);
        const float4* wsr = reinterpret_cast<const float4*>(sW + j * 128 + cb);
        const float4* war = reinterpret_cast<const float4*>(sW + j * 128 + 64 + cb);
        float4 ws0 = wsr[0], ws1 = wsr[1];
        float4 wa0 = war[0], wa1 = war[1];
        float wsv[8] = {ws0.x, ws0.y, ws0.z, ws0.w, ws1.x, ws1.y, ws1.z, ws1.w};
        float wav[8] = {wa0.x, wa0.y, wa0.z, wa0.w, wa1.x, wa1.y, wa1.z, wa1.w};
#pragma unroll
        for (int ci = 0; ci < 8; ++ci) {
            unsigned long long ws2 = dup2(wsv[ci]);
            unsigned long long wa2 = dup2(wav[ci]);
            ffma2(accS[ci * 4 + 0], ws2, h0.x);
            ffma2(accS[ci * 4 + 1], ws2, h0.y);
            ffma2(accS[ci * 4 + 2], ws2, h1.x);
            ffma2(accS[ci * 4 + 3], ws2, h1.y);
            ffma2(accA[ci * 4 + 0], wa2, h0.x);
            ffma2(accA[ci * 4 + 1], wa2, h0.y);
            ffma2(accA[ci * 4 + 2], wa2, h1.x);
            ffma2(accA[ci * 4 + 3], wa2, h1.y);
        }
    }
    __syncthreads();   // everyone done reading sH/sW before overwrite

    // ---- Phase C: H1 = relu(accA) -> sH ; Wb -> sW mat slot 0 ----
#pragma unroll
    for (int ci = 0; ci < 8; ++ci) {
#pragma unroll
        for (int mi = 0; mi < 2; ++mi) {
#pragma unroll
            for (int kp = 0; kp < 2; ++kp) {
                float2 v = unpack2(accA[ci * 4 + mi * 2 + kp]);
                v.x = fmaxf(v.x, 0.f);
                v.y = fmaxf(v.y, 0.f);
                *reinterpret_cast<float2*>(
                    sH + mi * 4096 + (cb + ci) * 64 + kb + kp * 2) = v;
            }
        }
    }
    for (int i = tid; i < 4096; i += 128) {
        int j = i >> 6, c = i & 63;
        sW[j * 128 + c] = g_WbT[i];
    }
    __syncthreads();

    // ---- Phase D: fcn1b GEMM ----
    unsigned long long accB[32];
#pragma unroll
    for (int ci = 0; ci < 8; ++ci) {
        unsigned long long tb = dup2(g_t1b[cb + ci]);
        accB[ci * 4 + 0] = tb; accB[ci * 4 + 1] = tb;
        accB[ci * 4 + 2] = tb; accB[ci * 4 + 3] = tb;
    }
#pragma unroll 2
    for (int j = 0; j < 64; ++j) {
        ulonglong2 h0 = *reinterpret_cast<const ulonglong2*>(sH + j * 64 + kb);
        ulonglong2 h1 = *reinterpret_cast<const ulonglong2*>(sH + 4096 + j * 64 + kb);
        const float4* wbr = reinterpret_cast<const float4*>(sW + j * 128 + cb);
        float4 wb0 = wbr[0], wb1 = wbr[1];
        float wbv[8] = {wb0.x, wb0.y, wb0.z, wb0.w, wb1.x, wb1.y, wb1.z, wb1.w};
#pragma unroll
        for (int ci = 0; ci < 8; ++ci) {
            unsigned long long wb2 = dup2(wbv[ci]);
            ffma2(accB[ci * 4 + 0], wb2, h0.x);
            ffma2(accB[ci * 4 + 1], wb2, h0.y);
            ffma2(accB[ci * 4 + 2], wb2, h1.x);
            ffma2(accB[ci * 4 + 3], wb2, h1.y);
        }
    }

    // ---- Phase E: F = relu(accB) + accS; max over this lane's 4 k's,
    //      then shfl-max over the 16 tk lanes (half-warp) ----
    float mx[16];   // [ci*2 + mi]
#pragma unroll
    for (int ci = 0; ci < 8; ++ci) {
#pragma unroll
        for (int mi = 0; mi < 2; ++mi) {
            float2 b0 = unpack2(accB[ci * 4 + mi * 2 + 0]);
            float2 b1 = unpack2(accB[ci * 4 + mi * 2 + 1]);
            float2 s0 = unpack2(accS[ci * 4 + mi * 2 + 0]);
            float2 s1 = unpack2(accS[ci * 4 + mi * 2 + 1]);
            float v0 = fmaxf(b0.x, 0.f) + s0.x;
            float v1 = fmaxf(b0.y, 0.f) + s0.y;
            float v2 = fmaxf(b1.x, 0.f) + s1.x;
            float v3 = fmaxf(b1.y, 0.f) + s1.y;
            mx[ci * 2 + mi] = fmaxf(fmaxf(v0, v1), fmaxf(v2, v3));
        }
    }
#pragma unroll
    for (int off = 8; off >= 1; off >>= 1) {
#pragma unroll
        for (int i = 0; i < 16; ++i)
            mx[i] = fmaxf(mx[i], __shfl_xor_sync(0xffffffffu, mx[i], off));
    }
    __syncthreads();                 // done reading sW — reuse as sF
    float* sF = sW;                  // [mi*64 + c]
    if (tk == 0) {
#pragma unroll
        for (int ci = 0; ci < 8; ++ci) {
            sF[0 * 64 + cb + ci] = mx[ci * 2 + 0];
            sF[1 * 64 + cb + ci] = mx[ci * 2 + 1];
        }
    }
    __syncthreads();

    // ---- Phase F: out[n][o][m] = Wout[o,:64]@sF + Wout[o,64:67]@pre_xyz ----
    if (w < 3) {
        int o = w;
#pragma unroll
        for (int mi = 0; mi < 2; ++mi) {
            int m = m0 + mi;
            float p = Wout[o * 67 + lane] * sF[mi * 64 + lane] +
                      Wout[o * 67 + 32 + lane] * sF[mi * 64 + 32 + lane];
#pragma unroll
            for (int off = 16; off >= 1; off >>= 1)
                p += __shfl_xor_sync(0xffffffffu, p, off);
            if (lane == 0) {
                p += Wout[o * 67 + 64] * pre_xyz[n * 3 * M_ + 0 * M_ + m] +
                     Wout[o * 67 + 65] * pre_xyz[n * 3 * M_ + 1 * M_ + m] +
                     Wout[o * 67 + 66] * pre_xyz[n * 3 * M_ + 2 * M_ + m];
                out[n * 3 * M_ + o * M_ + m] = p;
            }
        }
    }
}

// ---------------- launcher ----------------
extern "C" void kernel_launch(void* const* d_in, const int* in_sizes, int n_in,
                              void* d_out, int out_size)
{
    const float* query     = (const float*)d_in[0];
    const float* scene_rgb = (const float*)d_in[1];
    const float* scene_xyz = (const float*)d_in[2];
    const float* pre_xyz   = (const float*)d_in[3];
    const float* mask      = (const float*)d_in[4];
    const float* W0        = (const float*)d_in[5];
    const float* g0        = (const float*)d_in[6];
    const float* b0        = (const float*)d_in[7];
    const float* m0        = (const float*)d_in[8];
    const float* v0        = (const float*)d_in[9];
    const float* W1a       = (const float*)d_in[10];
    const float* g1a       = (const float*)d_in[11];
    const float* b1a       = (const float*)d_in[12];
    const float* m1a       = (const float*)d_in[13];
    const float* v1a       = (const float*)d_in[14];
    const float* W1b       = (const float*)d_in[15];
    const float* g1b       = (const float*)d_in[16];
    const float* b1b       = (const float*)d_in[17];
    const float* m1b       = (const float*)d_in[18];
    const float* v1b       = (const float*)d_in[19];
    const float* Wskip     = (const float*)d_in[20];
    const float* Wout      = (const float*)d_in[21];
    float* out = (float*)d_out;

    prep_weights<<<1, 256>>>(W1a, W1b, Wskip,
                             g0, b0, m0, v0,
                             g1a, b1a, m1a, v1a,
                             g1b, b1b, m1b, v1b);
    prep_nk<<<(N_ * C_ * K_) / 256, 256>>>(scene_rgb, scene_xyz, mask,
                                           W0, W1a, Wskip);
    prep_B0<<<(N_ * C_ * M_) / 256, 256>>>(query, W0);

    cudaFuncSetAttribute(fused_main, cudaFuncAttributeMaxDynamicSharedMemorySize,
                         65536);
    fused_main<<<N_ * (M_ / 2), 128, 65536>>>(pre_xyz, Wout, out);
}